// round 7
// baseline (speedup 1.0000x reference)
#include <cuda_runtime.h>
#include <cuda_fp16.h>
#include <cstdint>
#include <cstddef>

#define T_TOK 2048
#define HDIM  2048
#define NEXP  16
#define FDIM  1408
#define FSDIM 4096
#define TOPK  4
#define NPAIR (T_TOK*TOPK)
#define EGRP  4                    // experts per cvt/GEMM group
#define NGRP  (NEXP/EGRP)

// ---------------- scratch (static __device__, no allocs) ----------------
__device__ int   g_topk_idx[NPAIR];
__device__ float g_topk_w[NPAIR];
__device__ int   g_cnt[NEXP];
__device__ int   g_off[NEXP+1];
__device__ int   g_shared_off[2] = {0, T_TOK};
__device__ int   g_pair_token[NPAIR];
__device__ float g_pair_w[NPAIR];
__device__ int   g_inv[NPAIR];
__device__ __half g_xg_h[(size_t)NPAIR*HDIM];
__device__ __half g_h_h [(size_t)NPAIR*FDIM];
__device__ float  g_ybuf[(size_t)NPAIR*HDIM];
__device__ __half g_hs_h[(size_t)T_TOK*FSDIM];
__device__ __half g_xs_h[(size_t)T_TOK*HDIM];
__device__ __half g_Wg_h [(size_t)NEXP*HDIM*FDIM];
__device__ __half g_Wu_h [(size_t)NEXP*HDIM*FDIM];
__device__ __half g_Wd_h [(size_t)NEXP*FDIM*HDIM];
__device__ __half g_Wgs_h[(size_t)HDIM*FSDIM];
__device__ __half g_Wus_h[(size_t)HDIM*FSDIM];
__device__ __half g_Wds_h[(size_t)FSDIM*HDIM];

// ---------------- helpers ----------------
__device__ __forceinline__ uint32_t smem_u32(const void* p) {
    uint32_t a;
    asm("{ .reg .u64 t; cvta.to.shared.u64 t, %1; cvt.u32.u64 %0, t; }" : "=r"(a) : "l"(p));
    return a;
}
__device__ __forceinline__ void cpa16(uint32_t dst, const void* src, bool valid) {
    int sz = valid ? 16 : 0;
    asm volatile("cp.async.cg.shared.global [%0], [%1], 16, %2;\n" :: "r"(dst), "l"(src), "r"(sz));
}
__device__ __forceinline__ void cpa_commit() { asm volatile("cp.async.commit_group;\n" ::: "memory"); }
__device__ __forceinline__ void cpa_wait2()  { asm volatile("cp.async.wait_group 2;\n" ::: "memory"); }
__device__ __forceinline__ void cpa_wait1()  { asm volatile("cp.async.wait_group 1;\n" ::: "memory"); }
__device__ __forceinline__ void cpa_wait0()  { asm volatile("cp.async.wait_group 0;\n" ::: "memory"); }

__device__ __forceinline__ void ldsm4(uint32_t* r, uint32_t a) {
    asm volatile("ldmatrix.sync.aligned.m8n8.x4.shared.b16 {%0,%1,%2,%3}, [%4];"
                 : "=r"(r[0]), "=r"(r[1]), "=r"(r[2]), "=r"(r[3]) : "r"(a));
}
__device__ __forceinline__ void ldsm4t(uint32_t* r, uint32_t a) {
    asm volatile("ldmatrix.sync.aligned.m8n8.x4.trans.shared.b16 {%0,%1,%2,%3}, [%4];"
                 : "=r"(r[0]), "=r"(r[1]), "=r"(r[2]), "=r"(r[3]) : "r"(a));
}
__device__ __forceinline__ void mma16(float* c, const uint32_t* a, uint32_t b0, uint32_t b1) {
    asm volatile("mma.sync.aligned.m16n8k16.row.col.f32.f16.f16.f32 "
                 "{%0,%1,%2,%3},{%4,%5,%6,%7},{%8,%9},{%0,%1,%2,%3};"
                 : "+f"(c[0]), "+f"(c[1]), "+f"(c[2]), "+f"(c[3])
                 : "r"(a[0]), "r"(a[1]), "r"(a[2]), "r"(a[3]), "r"(b0), "r"(b1));
}

// ---------------- fp32 -> fp16 conversion (MLP=4) ----------------
__global__ void cvt16_kernel(const float4* __restrict__ src, uint2* __restrict__ dst, int n4)
{
    int i0 = blockIdx.x * 1024 + threadIdx.x;
    float4 v[4];
#pragma unroll
    for (int j = 0; j < 4; j++) v[j] = src[i0 + j*256];
#pragma unroll
    for (int j = 0; j < 4; j++) {
        __half2 h0 = __floats2half2_rn(v[j].x, v[j].y);
        __half2 h1 = __floats2half2_rn(v[j].z, v[j].w);
        uint2 u;
        u.x = *(uint32_t*)&h0; u.y = *(uint32_t*)&h1;
        dst[i0 + j*256] = u;
    }
}

// ---------------- router ----------------
__global__ void router_kernel(const float* __restrict__ x, const float* __restrict__ wr)
{
    int lane = threadIdx.x & 31;
    int t = blockIdx.x * 4 + (threadIdx.x >> 5);
    float acc[NEXP];
#pragma unroll
    for (int e = 0; e < NEXP; e++) acc[e] = 0.f;
    const float* xr = x + (size_t)t * HDIM;
    for (int h = lane; h < HDIM; h += 32) {
        float xv = xr[h];
#pragma unroll
        for (int e = 0; e < NEXP; e++) acc[e] += xv * wr[e*HDIM + h];
    }
#pragma unroll
    for (int e = 0; e < NEXP; e++) {
#pragma unroll
        for (int s = 16; s > 0; s >>= 1)
            acc[e] += __shfl_xor_sync(0xffffffffu, acc[e], s);
    }
    if (lane == 0) {
        int idx[TOPK]; float lv[TOPK];
#pragma unroll
        for (int k = 0; k < TOPK; k++) {
            int bi = 0; float bv = -1e30f;
#pragma unroll
            for (int e = 0; e < NEXP; e++)
                if (acc[e] > bv) { bv = acc[e]; bi = e; }
            idx[k] = bi; lv[k] = bv; acc[bi] = -1e30f;
        }
        float w[TOPK]; float s = 0.f;
#pragma unroll
        for (int k = 0; k < TOPK; k++) { w[k] = expf(lv[k] - lv[0]); s += w[k]; }
        float inv = 1.f / s;
#pragma unroll
        for (int k = 0; k < TOPK; k++) {
            g_topk_idx[t*TOPK+k] = idx[k];
            g_topk_w [t*TOPK+k] = w[k] * inv;
        }
    }
}

// ---------------- bucket construction (deterministic) ----------------
__global__ void count_kernel()
{
    int e = blockIdx.x;
    __shared__ int c;
    if (threadIdx.x == 0) c = 0;
    __syncthreads();
    int local = 0;
    for (int t = threadIdx.x; t < T_TOK; t += blockDim.x) {
#pragma unroll
        for (int k = 0; k < TOPK; k++) local += (g_topk_idx[t*TOPK+k] == e);
    }
    atomicAdd(&c, local);
    __syncthreads();
    if (threadIdx.x == 0) g_cnt[e] = c;
}

__global__ void scan_kernel()
{
    int s = 0;
    for (int e = 0; e < NEXP; e++) { g_off[e] = s; s += g_cnt[e]; }
    g_off[NEXP] = s;
}

__global__ void build_kernel()
{
    int e = blockIdx.x;
    int tid = threadIdx.x;
    __shared__ int sbase;
    __shared__ int sc[256];
    if (tid == 0) sbase = g_off[e];
    __syncthreads();
    for (int t0 = 0; t0 < T_TOK; t0 += 256) {
        int t = t0 + tid;
        int kf = -1;
#pragma unroll
        for (int k = 0; k < TOPK; k++)
            if (g_topk_idx[t*TOPK+k] == e) kf = k;
        int f = (kf >= 0) ? 1 : 0;
        sc[tid] = f;
        __syncthreads();
        for (int d = 1; d < 256; d <<= 1) {
            int v = (tid >= d) ? sc[tid-d] : 0;
            __syncthreads();
            sc[tid] += v;
            __syncthreads();
        }
        int incl = sc[tid];
        int tot  = sc[255];
        if (f) {
            int p = sbase + incl - 1;
            g_pair_token[p] = t;
            g_pair_w[p]     = g_topk_w[t*TOPK+kf];
            g_inv[t*TOPK+kf] = p;
        }
        __syncthreads();
        if (tid == 0) sbase += tot;
        __syncthreads();
    }
}

// ---------------- gather scaled inputs (fp16) ----------------
__global__ void gather_kernel(const float* __restrict__ x)
{
    int i = blockIdx.x * 256 + threadIdx.x;
    int p = i >> 9;
    int c = i & 511;
    float w = g_pair_w[p];
    int t = g_pair_token[p];
    float4 v = ((const float4*)x)[(size_t)t*512 + c];
    __half2 h0 = __floats2half2_rn(v.x*w, v.y*w);
    __half2 h1 = __floats2half2_rn(v.z*w, v.w*w);
    uint2 u;
    u.x = *(uint32_t*)&h0; u.y = *(uint32_t*)&h1;
    ((uint2*)g_xg_h)[(size_t)p*512 + c] = u;
}

// ---------------- fp16 mma GEMM kernels (3-stage cp.async) ----------------
#define A_TBYTES  10240
#define GU_BBYTES 4608     // 32*144
#define DN_BBYTES 8704     // 32*272
#define GU_STAGE  (A_TBYTES + 2*GU_BBYTES)   // 19456
#define DN_STAGE  (A_TBYTES + DN_BBYTES)     // 18944
#define NSTAGE    3
#define GU_SMEM   (NSTAGE*GU_STAGE)          // 58368
#define DN_SMEM   (NSTAGE*DN_STAGE)          // 56832

// fused gate+up: Hout[rows, N](fp16) = silu(A@Wg) * (A@Wu). BM=128, BN=64.
__global__ void __launch_bounds__(256, 2)
hgateup(const __half* __restrict__ A,
        const __half* __restrict__ Wg,
        const __half* __restrict__ Wu,
        const int* __restrict__ off,
        __half* __restrict__ Hout,
        int N, int K, size_t wstride, int zbase)
{
    int z = blockIdx.z + zbase;
    int row0 = off[z];
    int nrows = off[z+1] - row0;
    int m0 = blockIdx.y * 128;
    if (m0 >= nrows) return;
    int n0 = blockIdx.x * 64;
    const __half* Ab  = A  + (size_t)row0 * K;
    const __half* Wgb = Wg + (size_t)z * wstride;
    const __half* Wub = Wu + (size_t)z * wstride;

    extern __shared__ __align__(16) char smem[];
    uint32_t base0 = smem_u32(smem);

    int tid = threadIdx.x;
    int lane = tid & 31, wid = tid >> 5;
    int wm = (wid >> 1) * 32;
    int wn = (wid & 1) * 32;

    bool a_ok[2];
#pragma unroll
    for (int i = 0; i < 2; i++) a_ok[i] = (m0 + ((tid + i*256) >> 2)) < nrows;

    auto issue = [&](int ti, int s) {
        int kt = ti * 32;
        uint32_t sA = base0 + (uint32_t)s * GU_STAGE;
#pragma unroll
        for (int i = 0; i < 2; i++) {
            int id = tid + i*256;
            int r = id >> 2, c = id & 3;
            cpa16(sA + (uint32_t)(r*80 + c*16),
                  Ab + (size_t)(m0+r)*K + kt + c*8, a_ok[i]);
        }
        uint32_t sG = sA + A_TBYTES, sU = sG + GU_BBYTES;
        int kr = tid >> 3, c16 = tid & 7;
        size_t so = (size_t)(kt + kr) * N + n0 + c16*8;
        uint32_t doff = (uint32_t)(kr*144 + c16*16);
        cpa16(sG + doff, Wgb + so, true);
        cpa16(sU + doff, Wub + so, true);
        cpa_commit();
    };

    float accG[2][4][4], accU[2][4][4];
#pragma unroll
    for (int i = 0; i < 2; i++)
#pragma unroll
        for (int j = 0; j < 4; j++)
#pragma unroll
            for (int q = 0; q < 4; q++) { accG[i][j][q] = 0.f; accU[i][j][q] = 0.f; }

    int ntiles = K / 32;
    issue(0, 0);
    issue(1, 1);
    for (int ti = 0; ti < ntiles; ti++) {
        int s = ti % NSTAGE;
        if (ti + 2 < ntiles) { issue(ti + 2, (ti + 2) % NSTAGE); cpa_wait2(); }
        else if (ti + 1 < ntiles) cpa_wait1();
        else cpa_wait0();
        __syncthreads();

        uint32_t sA = base0 + (uint32_t)s * GU_STAGE;
        uint32_t sG = sA + A_TBYTES, sU = sG + GU_BBYTES;

#pragma unroll
        for (int ks2 = 0; ks2 < 2; ks2++) {
            int kb = ks2 * 16;
            uint32_t a[2][4];
#pragma unroll
            for (int mi = 0; mi < 2; mi++)
                ldsm4(a[mi], sA + (uint32_t)((wm + mi*16 + (lane & 15))*80
                                             + kb*2 + (lane >> 4)*16));
            uint32_t bg[2][4], bu[2][4];
#pragma unroll
            for (int t = 0; t < 2; t++) {
                uint32_t ba = sG + (uint32_t)((kb + (lane & 15))*144
                                              + (wn + t*16)*2 + (lane >> 4)*16);
                ldsm4t(bg[t], ba);
                ldsm4t(bu[t], ba + GU_BBYTES);
            }
#pragma unroll
            for (int mi = 0; mi < 2; mi++)
#pragma unroll
                for (int t = 0; t < 2; t++)
#pragma unroll
                    for (int hh = 0; hh < 2; hh++) {
                        mma16(accG[mi][t*2+hh], a[mi], bg[t][hh*2], bg[t][hh*2+1]);
                        mma16(accU[mi][t*2+hh], a[mi], bu[t][hh*2], bu[t][hh*2+1]);
                    }
        }
        __syncthreads();
    }

#pragma unroll
    for (int mi = 0; mi < 2; mi++)
#pragma unroll
        for (int ni = 0; ni < 4; ni++) {
            int rbase = wm + mi*16 + (lane >> 2);
            int cbase = wn + ni*8 + (lane & 3)*2;
#pragma unroll
            for (int hh = 0; hh < 2; hh++) {
                int r = rbase + hh*8;
                if (m0 + r < nrows) {
                    float g0 = accG[mi][ni][hh*2+0], g1 = accG[mi][ni][hh*2+1];
                    float u0 = accU[mi][ni][hh*2+0], u1 = accU[mi][ni][hh*2+1];
                    float h0 = g0 / (1.f + __expf(-g0)) * u0;
                    float h1 = g1 / (1.f + __expf(-g1)) * u1;
                    __half2 hv = __floats2half2_rn(h0, h1);
                    *(__half2*)(Hout + (size_t)(row0 + m0 + r) * N + n0 + cbase) = hv;
                }
            }
        }
}

// down: Out[rows, N](fp32) = (A@W)*scale[row]. BM=128, BN=128.
__global__ void __launch_bounds__(256, 2)
hdown(const __half* __restrict__ A,
      const __half* __restrict__ W,
      const int* __restrict__ off,
      const float* __restrict__ scale,
      float* __restrict__ Out,
      int N, int K, size_t wstride)
{
    int z = blockIdx.z;
    int row0 = off[z];
    int nrows = off[z+1] - row0;
    int m0 = blockIdx.y * 128;
    if (m0 >= nrows) return;
    int n0 = blockIdx.x * 128;
    const __half* Ab = A + (size_t)row0 * K;
    const __half* Wb = W + (size_t)z * wstride;

    extern __shared__ __align__(16) char smem[];
    uint32_t base0 = smem_u32(smem);

    int tid = threadIdx.x;
    int lane = tid & 31, wid = tid >> 5;
    int wm = (wid >> 2) * 64;
    int wn = (wid & 3) * 32;

    bool a_ok[2];
#pragma unroll
    for (int i = 0; i < 2; i++) a_ok[i] = (m0 + ((tid + i*256) >> 2)) < nrows;

    auto issue = [&](int ti, int s) {
        int kt = ti * 32;
        uint32_t sA = base0 + (uint32_t)s * DN_STAGE;
#pragma unroll
        for (int i = 0; i < 2; i++) {
            int id = tid + i*256;
            int r = id >> 2, c = id & 3;
            cpa16(sA + (uint32_t)(r*80 + c*16),
                  Ab + (size_t)(m0+r)*K + kt + c*8, a_ok[i]);
        }
        uint32_t sB = sA + A_TBYTES;
#pragma unroll
        for (int i = 0; i < 2; i++) {
            int id = tid + i*256;
            int kr = id >> 4, c16 = id & 15;
            cpa16(sB + (uint32_t)(kr*272 + c16*16),
                  Wb + (size_t)(kt+kr)*N + n0 + c16*8, true);
        }
        cpa_commit();
    };

    float acc[4][4][4];
#pragma unroll
    for (int i = 0; i < 4; i++)
#pragma unroll
        for (int j = 0; j < 4; j++)
#pragma unroll
            for (int q = 0; q < 4; q++) acc[i][j][q] = 0.f;

    int ntiles = K / 32;
    issue(0, 0);
    issue(1, 1);
    for (int ti = 0; ti < ntiles; ti++) {
        int s = ti % NSTAGE;
        if (ti + 2 < ntiles) { issue(ti + 2, (ti + 2) % NSTAGE); cpa_wait2(); }
        else if (ti + 1 < ntiles) cpa_wait1();
        else cpa_wait0();
        __syncthreads();

        uint32_t sA = base0 + (uint32_t)s * DN_STAGE;
        uint32_t sB = sA + A_TBYTES;

#pragma unroll
        for (int ks2 = 0; ks2 < 2; ks2++) {
            int kb = ks2 * 16;
            uint32_t a[4][4];
#pragma unroll
            for (int mi = 0; mi < 4; mi++)
                ldsm4(a[mi], sA + (uint32_t)((wm + mi*16 + (lane & 15))*80
                                             + kb*2 + (lane >> 4)*16));
            uint32_t b[2][4];
#pragma unroll
            for (int t = 0; t < 2; t++)
                ldsm4t(b[t], sB + (uint32_t)((kb + (lane & 15))*272
                                             + (wn + t*16)*2 + (lane >> 4)*16));
#pragma unroll
            for (int mi = 0; mi < 4; mi++)
#pragma unroll
                for (int t = 0; t < 2; t++)
#pragma unroll
                    for (int hh = 0; hh < 2; hh++)
                        mma16(acc[mi][t*2+hh], a[mi], b[t][hh*2], b[t][hh*2+1]);
        }
        __syncthreads();
    }

#pragma unroll
    for (int mi = 0; mi < 4; mi++)
#pragma unroll
        for (int ni = 0; ni < 4; ni++) {
            int rbase = wm + mi*16 + (lane >> 2);
            int cbase = wn + ni*8 + (lane & 3)*2;
#pragma unroll
            for (int hh = 0; hh < 2; hh++) {
                int r = rbase + hh*8;
                if (m0 + r < nrows) {
                    float sc = scale ? scale[row0 + m0 + r] : 1.f;
                    float2 v;
                    v.x = acc[mi][ni][hh*2+0] * sc;
                    v.y = acc[mi][ni][hh*2+1] * sc;
                    *(float2*)(Out + (size_t)(row0 + m0 + r) * N + n0 + cbase) = v;
                }
            }
        }
}

// ---------------- combine ----------------
__global__ void combine_kernel(float* __restrict__ out)
{
    int i = blockIdx.x * 256 + threadIdx.x;
    int t = i >> 9;
    int c = i & 511;
    float4 o = ((float4*)out)[i];
    const float4* y4 = (const float4*)g_ybuf;
#pragma unroll
    for (int k = 0; k < TOPK; k++) {
        int p = g_inv[t*TOPK+k];
        float4 v = y4[(size_t)p*512 + c];
        o.x += v.x; o.y += v.y; o.z += v.z; o.w += v.w;
    }
    ((float4*)out)[i] = o;
}

// ---------------- launch ----------------
extern "C" void kernel_launch(void* const* d_in, const int* in_sizes, int n_in,
                              void* d_out, int out_size)
{
    (void)in_sizes; (void)n_in; (void)out_size;
    const float* x   = (const float*)d_in[0];
    const float* wr  = (const float*)d_in[1];
    const float* Wg  = (const float*)d_in[2];
    const float* Wu  = (const float*)d_in[3];
    const float* Wd  = (const float*)d_in[4];
    const float* Wgs = (const float*)d_in[5];
    const float* Wus = (const float*)d_in[6];
    const float* Wds = (const float*)d_in[7];
    float* out = (float*)d_out;

    void *p_xg, *p_h, *p_y, *p_hs, *p_xs, *p_off, *p_soff, *p_pw;
    void *p_wg, *p_wu, *p_wd, *p_wgs, *p_wus, *p_wds;
    cudaGetSymbolAddress(&p_xg,  g_xg_h);
    cudaGetSymbolAddress(&p_h,   g_h_h);
    cudaGetSymbolAddress(&p_y,   g_ybuf);
    cudaGetSymbolAddress(&p_hs,  g_hs_h);
    cudaGetSymbolAddress(&p_xs,  g_xs_h);
    cudaGetSymbolAddress(&p_off, g_off);
    cudaGetSymbolAddress(&p_soff, g_shared_off);
    cudaGetSymbolAddress(&p_pw,  g_pair_w);
    cudaGetSymbolAddress(&p_wg,  g_Wg_h);
    cudaGetSymbolAddress(&p_wu,  g_Wu_h);
    cudaGetSymbolAddress(&p_wd,  g_Wd_h);
    cudaGetSymbolAddress(&p_wgs, g_Wgs_h);
    cudaGetSymbolAddress(&p_wus, g_Wus_h);
    cudaGetSymbolAddress(&p_wds, g_Wds_h);

    // one-time resources
    static cudaStream_t sB = nullptr, sC = nullptr;
    static cudaEvent_t evRoot, evG[NGRP], evWd, evShared;
    if (!sB) {
        cudaStreamCreateWithFlags(&sB, cudaStreamNonBlocking);
        cudaStreamCreateWithFlags(&sC, cudaStreamNonBlocking);
        cudaEventCreateWithFlags(&evRoot,   cudaEventDisableTiming);
        for (int g = 0; g < NGRP; g++)
            cudaEventCreateWithFlags(&evG[g], cudaEventDisableTiming);
        cudaEventCreateWithFlags(&evWd,     cudaEventDisableTiming);
        cudaEventCreateWithFlags(&evShared, cudaEventDisableTiming);
        cudaFuncSetAttribute(hgateup, cudaFuncAttributeMaxDynamicSharedMemorySize, GU_SMEM);
        cudaFuncSetAttribute(hdown,   cudaFuncAttributeMaxDynamicSharedMemorySize, DN_SMEM);
    }

    const int NEF4  = NEXP*HDIM*FDIM/4;       // all-expert float4 count
    const int GRP4  = NEF4/NGRP;              // per-group float4 count (2883584, %1024==0)
    const size_t GRPELEM = (size_t)EGRP*HDIM*FDIM;
    const int NSH4 = HDIM*FSDIM/4;
    const int NX4  = T_TOK*HDIM/4;

    // fork side streams
    cudaEventRecord(evRoot, 0);
    cudaStreamWaitEvent(sB, evRoot, 0);
    cudaStreamWaitEvent(sC, evRoot, 0);

    // stream B: per-group Wg/Wu cvt (events per group), then Wd cvt
    for (int g = 0; g < NGRP; g++) {
        cvt16_kernel<<<GRP4/1024, 256, 0, sB>>>(
            (const float4*)(Wg + g*GRPELEM), (uint2*)((__half*)p_wg + g*GRPELEM), GRP4);
        cvt16_kernel<<<GRP4/1024, 256, 0, sB>>>(
            (const float4*)(Wu + g*GRPELEM), (uint2*)((__half*)p_wu + g*GRPELEM), GRP4);
        cudaEventRecord(evG[g], sB);
    }
    cvt16_kernel<<<NEF4/1024, 256, 0, sB>>>((const float4*)Wd, (uint2*)p_wd, NEF4);
    cudaEventRecord(evWd, sB);

    // stream C: shared-expert chain; Wds cvt moved after gateup launch
    cvt16_kernel<<<NX4 /1024, 256, 0, sC>>>((const float4*)x,   (uint2*)p_xs,  NX4);
    cvt16_kernel<<<NSH4/1024, 256, 0, sC>>>((const float4*)Wgs, (uint2*)p_wgs, NSH4);
    cvt16_kernel<<<NSH4/1024, 256, 0, sC>>>((const float4*)Wus, (uint2*)p_wus, NSH4);
    hgateup<<<dim3(FSDIM/64, 16, 1), 256, GU_SMEM, sC>>>(
        (const __half*)p_xs, (const __half*)p_wgs, (const __half*)p_wus,
        (const int*)p_soff, (__half*)p_hs, FSDIM, HDIM, 0, 0);
    cvt16_kernel<<<NSH4/1024, 256, 0, sC>>>((const float4*)Wds, (uint2*)p_wds, NSH4);
    hdown<<<dim3(HDIM/128, 16, 1), 256, DN_SMEM, sC>>>(
        (const __half*)p_hs, (const __half*)p_wds, (const int*)p_soff,
        nullptr, out, HDIM, FSDIM, 0);     // writes d_out (overwrites poison)
    cudaEventRecord(evShared, sC);

    // stream 0: routing chain, then per-group expert gateup, then expert down
    router_kernel<<<T_TOK/4, 128>>>(x, wr);
    count_kernel<<<NEXP, 256>>>();
    scan_kernel<<<1, 1>>>();
    build_kernel<<<NEXP, 256>>>();
    gather_kernel<<<NPAIR*(HDIM/4)/256, 256>>>(x);

    for (int g = 0; g < NGRP; g++) {
        cudaStreamWaitEvent(0, evG[g], 0);
        hgateup<<<dim3(FDIM/64, 16, EGRP), 256, GU_SMEM>>>(
            (const __half*)p_xg, (const __half*)p_wg, (const __half*)p_wu,
            (const int*)p_off, (__half*)p_h, FDIM, HDIM, (size_t)HDIM*FDIM, g*EGRP);
    }

    cudaStreamWaitEvent(0, evWd, 0);
    hdown<<<dim3(HDIM/128, 16, NEXP), 256, DN_SMEM>>>(
        (const __half*)p_h, (const __half*)p_wd, (const int*)p_off,
        (const float*)p_pw, (float*)p_y, HDIM, FDIM, (size_t)FDIM*HDIM);

    cudaStreamWaitEvent(0, evShared, 0);
    combine_kernel<<<T_TOK*(HDIM/4)/256, 256>>>(out);
}

// round 8
// speedup vs baseline: 1.1477x; 1.1477x over previous
#include <cuda_runtime.h>
#include <cuda_fp16.h>
#include <cstdint>
#include <cstddef>

#define T_TOK 2048
#define HDIM  2048
#define NEXP  16
#define FDIM  1408
#define FSDIM 4096
#define TOPK  4
#define NPAIR (T_TOK*TOPK)

// ---------------- scratch (static __device__, no allocs) ----------------
__device__ int   g_topk_idx[NPAIR];
__device__ float g_topk_w[NPAIR];
__device__ int   g_cnt[NEXP];
__device__ int   g_off[NEXP+1];
__device__ int   g_shared_off[2] = {0, T_TOK};
__device__ int   g_pair_token[NPAIR];
__device__ float g_pair_w[NPAIR];
__device__ int   g_inv[NPAIR];
__device__ __half g_xg_h[(size_t)NPAIR*HDIM];
__device__ __half g_h_h [(size_t)NPAIR*FDIM];
__device__ float  g_ybuf[(size_t)NPAIR*HDIM];
__device__ __half g_hs_h[(size_t)T_TOK*FSDIM];
__device__ __half g_xs_h[(size_t)T_TOK*HDIM];
__device__ __half g_Wg_h [(size_t)NEXP*HDIM*FDIM];
__device__ __half g_Wu_h [(size_t)NEXP*HDIM*FDIM];
__device__ __half g_Wd_h [(size_t)NEXP*FDIM*HDIM];
__device__ __half g_Wgs_h[(size_t)HDIM*FSDIM];
__device__ __half g_Wus_h[(size_t)HDIM*FSDIM];
__device__ __half g_Wds_h[(size_t)FSDIM*HDIM];

// ---------------- helpers ----------------
__device__ __forceinline__ uint32_t smem_u32(const void* p) {
    uint32_t a;
    asm("{ .reg .u64 t; cvta.to.shared.u64 t, %1; cvt.u32.u64 %0, t; }" : "=r"(a) : "l"(p));
    return a;
}
__device__ __forceinline__ void cpa16(uint32_t dst, const void* src, bool valid) {
    int sz = valid ? 16 : 0;
    asm volatile("cp.async.cg.shared.global [%0], [%1], 16, %2;\n" :: "r"(dst), "l"(src), "r"(sz));
}
__device__ __forceinline__ void cpa_commit() { asm volatile("cp.async.commit_group;\n" ::: "memory"); }
__device__ __forceinline__ void cpa_wait2()  { asm volatile("cp.async.wait_group 2;\n" ::: "memory"); }
__device__ __forceinline__ void cpa_wait1()  { asm volatile("cp.async.wait_group 1;\n" ::: "memory"); }
__device__ __forceinline__ void cpa_wait0()  { asm volatile("cp.async.wait_group 0;\n" ::: "memory"); }

__device__ __forceinline__ void ldsm4(uint32_t* r, uint32_t a) {
    asm volatile("ldmatrix.sync.aligned.m8n8.x4.shared.b16 {%0,%1,%2,%3}, [%4];"
                 : "=r"(r[0]), "=r"(r[1]), "=r"(r[2]), "=r"(r[3]) : "r"(a));
}
__device__ __forceinline__ void ldsm4t(uint32_t* r, uint32_t a) {
    asm volatile("ldmatrix.sync.aligned.m8n8.x4.trans.shared.b16 {%0,%1,%2,%3}, [%4];"
                 : "=r"(r[0]), "=r"(r[1]), "=r"(r[2]), "=r"(r[3]) : "r"(a));
}
__device__ __forceinline__ void mma16(float* c, const uint32_t* a, uint32_t b0, uint32_t b1) {
    asm volatile("mma.sync.aligned.m16n8k16.row.col.f32.f16.f16.f32 "
                 "{%0,%1,%2,%3},{%4,%5,%6,%7},{%8,%9},{%0,%1,%2,%3};"
                 : "+f"(c[0]), "+f"(c[1]), "+f"(c[2]), "+f"(c[3])
                 : "r"(a[0]), "r"(a[1]), "r"(a[2]), "r"(a[3]), "r"(b0), "r"(b1));
}

// ---------------- fp32 -> fp16 conversion (MLP=4) ----------------
__global__ void cvt16_kernel(const float4* __restrict__ src, uint2* __restrict__ dst, int n4)
{
    int i0 = blockIdx.x * 1024 + threadIdx.x;
    float4 v[4];
#pragma unroll
    for (int j = 0; j < 4; j++) v[j] = src[i0 + j*256];
#pragma unroll
    for (int j = 0; j < 4; j++) {
        __half2 h0 = __floats2half2_rn(v[j].x, v[j].y);
        __half2 h1 = __floats2half2_rn(v[j].z, v[j].w);
        uint2 u;
        u.x = *(uint32_t*)&h0; u.y = *(uint32_t*)&h1;
        dst[i0 + j*256] = u;
    }
}

// ---------------- router ----------------
__global__ void router_kernel(const float* __restrict__ x, const float* __restrict__ wr)
{
    int lane = threadIdx.x & 31;
    int t = blockIdx.x * 4 + (threadIdx.x >> 5);
    float acc[NEXP];
#pragma unroll
    for (int e = 0; e < NEXP; e++) acc[e] = 0.f;
    const float* xr = x + (size_t)t * HDIM;
    for (int h = lane; h < HDIM; h += 32) {
        float xv = xr[h];
#pragma unroll
        for (int e = 0; e < NEXP; e++) acc[e] += xv * wr[e*HDIM + h];
    }
#pragma unroll
    for (int e = 0; e < NEXP; e++) {
#pragma unroll
        for (int s = 16; s > 0; s >>= 1)
            acc[e] += __shfl_xor_sync(0xffffffffu, acc[e], s);
    }
    if (lane == 0) {
        int idx[TOPK]; float lv[TOPK];
#pragma unroll
        for (int k = 0; k < TOPK; k++) {
            int bi = 0; float bv = -1e30f;
#pragma unroll
            for (int e = 0; e < NEXP; e++)
                if (acc[e] > bv) { bv = acc[e]; bi = e; }
            idx[k] = bi; lv[k] = bv; acc[bi] = -1e30f;
        }
        float w[TOPK]; float s = 0.f;
#pragma unroll
        for (int k = 0; k < TOPK; k++) { w[k] = expf(lv[k] - lv[0]); s += w[k]; }
        float inv = 1.f / s;
#pragma unroll
        for (int k = 0; k < TOPK; k++) {
            g_topk_idx[t*TOPK+k] = idx[k];
            g_topk_w [t*TOPK+k] = w[k] * inv;
        }
    }
}

// ---------------- bucket construction (deterministic) ----------------
__global__ void count_kernel()
{
    int e = blockIdx.x;
    __shared__ int c;
    if (threadIdx.x == 0) c = 0;
    __syncthreads();
    int local = 0;
    for (int t = threadIdx.x; t < T_TOK; t += blockDim.x) {
#pragma unroll
        for (int k = 0; k < TOPK; k++) local += (g_topk_idx[t*TOPK+k] == e);
    }
    atomicAdd(&c, local);
    __syncthreads();
    if (threadIdx.x == 0) g_cnt[e] = c;
}

__global__ void scan_kernel()
{
    int s = 0;
    for (int e = 0; e < NEXP; e++) { g_off[e] = s; s += g_cnt[e]; }
    g_off[NEXP] = s;
}

__global__ void build_kernel()
{
    int e = blockIdx.x;
    int tid = threadIdx.x;
    __shared__ int sbase;
    __shared__ int sc[256];
    if (tid == 0) sbase = g_off[e];
    __syncthreads();
    for (int t0 = 0; t0 < T_TOK; t0 += 256) {
        int t = t0 + tid;
        int kf = -1;
#pragma unroll
        for (int k = 0; k < TOPK; k++)
            if (g_topk_idx[t*TOPK+k] == e) kf = k;
        int f = (kf >= 0) ? 1 : 0;
        sc[tid] = f;
        __syncthreads();
        for (int d = 1; d < 256; d <<= 1) {
            int v = (tid >= d) ? sc[tid-d] : 0;
            __syncthreads();
            sc[tid] += v;
            __syncthreads();
        }
        int incl = sc[tid];
        int tot  = sc[255];
        if (f) {
            int p = sbase + incl - 1;
            g_pair_token[p] = t;
            g_pair_w[p]     = g_topk_w[t*TOPK+kf];
            g_inv[t*TOPK+kf] = p;
        }
        __syncthreads();
        if (tid == 0) sbase += tot;
        __syncthreads();
    }
}

// ---------------- gather scaled inputs (fp16) ----------------
__global__ void gather_kernel(const float* __restrict__ x)
{
    int i = blockIdx.x * 256 + threadIdx.x;
    int p = i >> 9;
    int c = i & 511;
    float w = g_pair_w[p];
    int t = g_pair_token[p];
    float4 v = ((const float4*)x)[(size_t)t*512 + c];
    __half2 h0 = __floats2half2_rn(v.x*w, v.y*w);
    __half2 h1 = __floats2half2_rn(v.z*w, v.w*w);
    uint2 u;
    u.x = *(uint32_t*)&h0; u.y = *(uint32_t*)&h1;
    ((uint2*)g_xg_h)[(size_t)p*512 + c] = u;
}

// ---------------- fp16 mma GEMM kernels (4-stage cp.async, 1 barrier/k-tile) ----------------
#define A_TBYTES  10240
#define GU_BBYTES 4608     // 32*144
#define DN_BBYTES 8704     // 32*272
#define GU_STAGE  (A_TBYTES + 2*GU_BBYTES)   // 19456
#define DN_STAGE  (A_TBYTES + DN_BBYTES)     // 18944
#define NSTAGE    4
#define GU_SMEM   (NSTAGE*GU_STAGE)          // 77824
#define DN_SMEM   (NSTAGE*DN_STAGE)          // 75776

// fused gate+up: Hout[rows, N](fp16) = silu(A@Wg) * (A@Wu). BM=128, BN=64.
__global__ void __launch_bounds__(256, 2)
hgateup(const __half* __restrict__ A,
        const __half* __restrict__ Wg,
        const __half* __restrict__ Wu,
        const int* __restrict__ off,
        __half* __restrict__ Hout,
        int N, int K, size_t wstride)
{
    int z = blockIdx.z;
    int row0 = off[z];
    int nrows = off[z+1] - row0;
    int m0 = blockIdx.y * 128;
    if (m0 >= nrows) return;
    int n0 = blockIdx.x * 64;
    const __half* Ab  = A  + (size_t)row0 * K;
    const __half* Wgb = Wg + (size_t)z * wstride;
    const __half* Wub = Wu + (size_t)z * wstride;

    extern __shared__ __align__(16) char smem[];
    uint32_t base0 = smem_u32(smem);

    int tid = threadIdx.x;
    int lane = tid & 31, wid = tid >> 5;
    int wm = (wid >> 1) * 32;
    int wn = (wid & 1) * 32;

    bool a_ok[2];
#pragma unroll
    for (int i = 0; i < 2; i++) a_ok[i] = (m0 + ((tid + i*256) >> 2)) < nrows;

    auto issue = [&](int ti) {
        int kt = ti * 32;
        uint32_t sA = base0 + (uint32_t)(ti & 3) * GU_STAGE;
#pragma unroll
        for (int i = 0; i < 2; i++) {
            int id = tid + i*256;
            int r = id >> 2, c = id & 3;
            cpa16(sA + (uint32_t)(r*80 + c*16),
                  Ab + (size_t)(m0+r)*K + kt + c*8, a_ok[i]);
        }
        uint32_t sG = sA + A_TBYTES, sU = sG + GU_BBYTES;
        int kr = tid >> 3, c16 = tid & 7;
        size_t so = (size_t)(kt + kr) * N + n0 + c16*8;
        uint32_t doff = (uint32_t)(kr*144 + c16*16);
        cpa16(sG + doff, Wgb + so, true);
        cpa16(sU + doff, Wub + so, true);
        cpa_commit();
    };

    float accG[2][4][4], accU[2][4][4];
#pragma unroll
    for (int i = 0; i < 2; i++)
#pragma unroll
        for (int j = 0; j < 4; j++)
#pragma unroll
            for (int q = 0; q < 4; q++) { accG[i][j][q] = 0.f; accU[i][j][q] = 0.f; }

    int ntiles = K / 32;
    issue(0); issue(1); issue(2);
    for (int ti = 0; ti < ntiles; ti++) {
        if (ti + 2 < ntiles) cpa_wait2();
        else if (ti + 1 < ntiles) cpa_wait1();
        else cpa_wait0();
        __syncthreads();
        // safe: barrier above guarantees all warps finished reading stage (ti-1)&3,
        // which is exactly the stage issue(ti+3) overwrites.
        if (ti + 3 < ntiles) issue(ti + 3);

        uint32_t sA = base0 + (uint32_t)(ti & 3) * GU_STAGE;
        uint32_t sG = sA + A_TBYTES, sU = sG + GU_BBYTES;

#pragma unroll
        for (int ks2 = 0; ks2 < 2; ks2++) {
            int kb = ks2 * 16;
            uint32_t a[2][4];
#pragma unroll
            for (int mi = 0; mi < 2; mi++)
                ldsm4(a[mi], sA + (uint32_t)((wm + mi*16 + (lane & 15))*80
                                             + kb*2 + (lane >> 4)*16));
            uint32_t bg[2][4], bu[2][4];
#pragma unroll
            for (int t = 0; t < 2; t++) {
                uint32_t ba = sG + (uint32_t)((kb + (lane & 15))*144
                                              + (wn + t*16)*2 + (lane >> 4)*16);
                ldsm4t(bg[t], ba);
                ldsm4t(bu[t], ba + GU_BBYTES);
            }
#pragma unroll
            for (int mi = 0; mi < 2; mi++)
#pragma unroll
                for (int t = 0; t < 2; t++)
#pragma unroll
                    for (int hh = 0; hh < 2; hh++) {
                        mma16(accG[mi][t*2+hh], a[mi], bg[t][hh*2], bg[t][hh*2+1]);
                        mma16(accU[mi][t*2+hh], a[mi], bu[t][hh*2], bu[t][hh*2+1]);
                    }
        }
    }

#pragma unroll
    for (int mi = 0; mi < 2; mi++)
#pragma unroll
        for (int ni = 0; ni < 4; ni++) {
            int rbase = wm + mi*16 + (lane >> 2);
            int cbase = wn + ni*8 + (lane & 3)*2;
#pragma unroll
            for (int hh = 0; hh < 2; hh++) {
                int r = rbase + hh*8;
                if (m0 + r < nrows) {
                    float g0 = accG[mi][ni][hh*2+0], g1 = accG[mi][ni][hh*2+1];
                    float u0 = accU[mi][ni][hh*2+0], u1 = accU[mi][ni][hh*2+1];
                    float h0 = g0 / (1.f + __expf(-g0)) * u0;
                    float h1 = g1 / (1.f + __expf(-g1)) * u1;
                    __half2 hv = __floats2half2_rn(h0, h1);
                    *(__half2*)(Hout + (size_t)(row0 + m0 + r) * N + n0 + cbase) = hv;
                }
            }
        }
}

// down: Out[rows, N](fp32) = (A@W)*scale[row]. BM=128, BN=128.
__global__ void __launch_bounds__(256, 2)
hdown(const __half* __restrict__ A,
      const __half* __restrict__ W,
      const int* __restrict__ off,
      const float* __restrict__ scale,
      float* __restrict__ Out,
      int N, int K, size_t wstride)
{
    int z = blockIdx.z;
    int row0 = off[z];
    int nrows = off[z+1] - row0;
    int m0 = blockIdx.y * 128;
    if (m0 >= nrows) return;
    int n0 = blockIdx.x * 128;
    const __half* Ab = A + (size_t)row0 * K;
    const __half* Wb = W + (size_t)z * wstride;

    extern __shared__ __align__(16) char smem[];
    uint32_t base0 = smem_u32(smem);

    int tid = threadIdx.x;
    int lane = tid & 31, wid = tid >> 5;
    int wm = (wid >> 2) * 64;
    int wn = (wid & 3) * 32;

    bool a_ok[2];
#pragma unroll
    for (int i = 0; i < 2; i++) a_ok[i] = (m0 + ((tid + i*256) >> 2)) < nrows;

    auto issue = [&](int ti) {
        int kt = ti * 32;
        uint32_t sA = base0 + (uint32_t)(ti & 3) * DN_STAGE;
#pragma unroll
        for (int i = 0; i < 2; i++) {
            int id = tid + i*256;
            int r = id >> 2, c = id & 3;
            cpa16(sA + (uint32_t)(r*80 + c*16),
                  Ab + (size_t)(m0+r)*K + kt + c*8, a_ok[i]);
        }
        uint32_t sB = sA + A_TBYTES;
#pragma unroll
        for (int i = 0; i < 2; i++) {
            int id = tid + i*256;
            int kr = id >> 4, c16 = id & 15;
            cpa16(sB + (uint32_t)(kr*272 + c16*16),
                  Wb + (size_t)(kt+kr)*N + n0 + c16*8, true);
        }
        cpa_commit();
    };

    float acc[4][4][4];
#pragma unroll
    for (int i = 0; i < 4; i++)
#pragma unroll
        for (int j = 0; j < 4; j++)
#pragma unroll
            for (int q = 0; q < 4; q++) acc[i][j][q] = 0.f;

    int ntiles = K / 32;
    issue(0); issue(1); issue(2);
    for (int ti = 0; ti < ntiles; ti++) {
        if (ti + 2 < ntiles) cpa_wait2();
        else if (ti + 1 < ntiles) cpa_wait1();
        else cpa_wait0();
        __syncthreads();
        if (ti + 3 < ntiles) issue(ti + 3);

        uint32_t sA = base0 + (uint32_t)(ti & 3) * DN_STAGE;
        uint32_t sB = sA + A_TBYTES;

#pragma unroll
        for (int ks2 = 0; ks2 < 2; ks2++) {
            int kb = ks2 * 16;
            uint32_t a[4][4];
#pragma unroll
            for (int mi = 0; mi < 4; mi++)
                ldsm4(a[mi], sA + (uint32_t)((wm + mi*16 + (lane & 15))*80
                                             + kb*2 + (lane >> 4)*16));
            uint32_t b[2][4];
#pragma unroll
            for (int t = 0; t < 2; t++)
                ldsm4t(b[t], sB + (uint32_t)((kb + (lane & 15))*272
                                             + (wn + t*16)*2 + (lane >> 4)*16));
#pragma unroll
            for (int mi = 0; mi < 4; mi++)
#pragma unroll
                for (int t = 0; t < 2; t++)
#pragma unroll
                    for (int hh = 0; hh < 2; hh++)
                        mma16(acc[mi][t*2+hh], a[mi], b[t][hh*2], b[t][hh*2+1]);
        }
    }

#pragma unroll
    for (int mi = 0; mi < 4; mi++)
#pragma unroll
        for (int ni = 0; ni < 4; ni++) {
            int rbase = wm + mi*16 + (lane >> 2);
            int cbase = wn + ni*8 + (lane & 3)*2;
#pragma unroll
            for (int hh = 0; hh < 2; hh++) {
                int r = rbase + hh*8;
                if (m0 + r < nrows) {
                    float sc = scale ? scale[row0 + m0 + r] : 1.f;
                    float2 v;
                    v.x = acc[mi][ni][hh*2+0] * sc;
                    v.y = acc[mi][ni][hh*2+1] * sc;
                    *(float2*)(Out + (size_t)(row0 + m0 + r) * N + n0 + cbase) = v;
                }
            }
        }
}

// ---------------- combine ----------------
__global__ void combine_kernel(float* __restrict__ out)
{
    int i = blockIdx.x * 256 + threadIdx.x;
    int t = i >> 9;
    int c = i & 511;
    float4 o = ((float4*)out)[i];
    const float4* y4 = (const float4*)g_ybuf;
#pragma unroll
    for (int k = 0; k < TOPK; k++) {
        int p = g_inv[t*TOPK+k];
        float4 v = y4[(size_t)p*512 + c];
        o.x += v.x; o.y += v.y; o.z += v.z; o.w += v.w;
    }
    ((float4*)out)[i] = o;
}

// ---------------- launch ----------------
extern "C" void kernel_launch(void* const* d_in, const int* in_sizes, int n_in,
                              void* d_out, int out_size)
{
    (void)in_sizes; (void)n_in; (void)out_size;
    const float* x   = (const float*)d_in[0];
    const float* wr  = (const float*)d_in[1];
    const float* Wg  = (const float*)d_in[2];
    const float* Wu  = (const float*)d_in[3];
    const float* Wd  = (const float*)d_in[4];
    const float* Wgs = (const float*)d_in[5];
    const float* Wus = (const float*)d_in[6];
    const float* Wds = (const float*)d_in[7];
    float* out = (float*)d_out;

    void *p_xg, *p_h, *p_y, *p_hs, *p_xs, *p_off, *p_soff, *p_pw;
    void *p_wg, *p_wu, *p_wd, *p_wgs, *p_wus, *p_wds;
    cudaGetSymbolAddress(&p_xg,  g_xg_h);
    cudaGetSymbolAddress(&p_h,   g_h_h);
    cudaGetSymbolAddress(&p_y,   g_ybuf);
    cudaGetSymbolAddress(&p_hs,  g_hs_h);
    cudaGetSymbolAddress(&p_xs,  g_xs_h);
    cudaGetSymbolAddress(&p_off, g_off);
    cudaGetSymbolAddress(&p_soff, g_shared_off);
    cudaGetSymbolAddress(&p_pw,  g_pair_w);
    cudaGetSymbolAddress(&p_wg,  g_Wg_h);
    cudaGetSymbolAddress(&p_wu,  g_Wu_h);
    cudaGetSymbolAddress(&p_wd,  g_Wd_h);
    cudaGetSymbolAddress(&p_wgs, g_Wgs_h);
    cudaGetSymbolAddress(&p_wus, g_Wus_h);
    cudaGetSymbolAddress(&p_wds, g_Wds_h);

    // one-time resources
    static cudaStream_t sB = nullptr, sC = nullptr;
    static cudaEvent_t evRoot, evWgu, evWd, evShared;
    if (!sB) {
        cudaStreamCreateWithFlags(&sB, cudaStreamNonBlocking);
        cudaStreamCreateWithFlags(&sC, cudaStreamNonBlocking);
        cudaEventCreateWithFlags(&evRoot,   cudaEventDisableTiming);
        cudaEventCreateWithFlags(&evWgu,    cudaEventDisableTiming);
        cudaEventCreateWithFlags(&evWd,     cudaEventDisableTiming);
        cudaEventCreateWithFlags(&evShared, cudaEventDisableTiming);
        cudaFuncSetAttribute(hgateup, cudaFuncAttributeMaxDynamicSharedMemorySize, GU_SMEM);
        cudaFuncSetAttribute(hdown,   cudaFuncAttributeMaxDynamicSharedMemorySize, DN_SMEM);
    }

    const int NEF4 = NEXP*HDIM*FDIM/4;
    const int NSH4 = HDIM*FSDIM/4;
    const int NX4  = T_TOK*HDIM/4;

    // fork side streams
    cudaEventRecord(evRoot, 0);
    cudaStreamWaitEvent(sB, evRoot, 0);
    cudaStreamWaitEvent(sC, evRoot, 0);

    // stream B: gate/up expert weights (gate first GEMM), then down weights
    cvt16_kernel<<<NEF4/1024, 256, 0, sB>>>((const float4*)Wg, (uint2*)p_wg, NEF4);
    cvt16_kernel<<<NEF4/1024, 256, 0, sB>>>((const float4*)Wu, (uint2*)p_wu, NEF4);
    cudaEventRecord(evWgu, sB);
    cvt16_kernel<<<NEF4/1024, 256, 0, sB>>>((const float4*)Wd, (uint2*)p_wd, NEF4);
    cudaEventRecord(evWd, sB);

    // stream C: shared-expert chain; Wds cvt after shared-gateup launch
    cvt16_kernel<<<NX4 /1024, 256, 0, sC>>>((const float4*)x,   (uint2*)p_xs,  NX4);
    cvt16_kernel<<<NSH4/1024, 256, 0, sC>>>((const float4*)Wgs, (uint2*)p_wgs, NSH4);
    cvt16_kernel<<<NSH4/1024, 256, 0, sC>>>((const float4*)Wus, (uint2*)p_wus, NSH4);
    hgateup<<<dim3(FSDIM/64, 16, 1), 256, GU_SMEM, sC>>>(
        (const __half*)p_xs, (const __half*)p_wgs, (const __half*)p_wus,
        (const int*)p_soff, (__half*)p_hs, FSDIM, HDIM, 0);
    cvt16_kernel<<<NSH4/1024, 256, 0, sC>>>((const float4*)Wds, (uint2*)p_wds, NSH4);
    hdown<<<dim3(HDIM/128, 16, 1), 256, DN_SMEM, sC>>>(
        (const __half*)p_hs, (const __half*)p_wds, (const int*)p_soff,
        nullptr, out, HDIM, FSDIM, 0);     // writes d_out (overwrites poison)
    cudaEventRecord(evShared, sC);

    // stream 0: routing chain, then expert GEMMs
    router_kernel<<<T_TOK/4, 128>>>(x, wr);
    count_kernel<<<NEXP, 256>>>();
    scan_kernel<<<1, 1>>>();
    build_kernel<<<NEXP, 256>>>();
    gather_kernel<<<NPAIR*(HDIM/4)/256, 256>>>(x);

    cudaStreamWaitEvent(0, evWgu, 0);
    hgateup<<<dim3(FDIM/64, 16, NEXP), 256, GU_SMEM>>>(
        (const __half*)p_xg, (const __half*)p_wg, (const __half*)p_wu,
        (const int*)p_off, (__half*)p_h, FDIM, HDIM, (size_t)HDIM*FDIM);

    cudaStreamWaitEvent(0, evWd, 0);
    hdown<<<dim3(HDIM/128, 16, NEXP), 256, DN_SMEM>>>(
        (const __half*)p_h, (const __half*)p_wd, (const int*)p_off,
        (const float*)p_pw, (float*)p_y, HDIM, FDIM, (size_t)FDIM*HDIM);

    cudaStreamWaitEvent(0, evShared, 0);
    combine_kernel<<<T_TOK*(HDIM/4)/256, 256>>>(out);
}